// round 3
// baseline (speedup 1.0000x reference)
#include <cuda_runtime.h>

// Problem shapes (fixed by the reference setup_inputs):
//   x:      [4, 2048, 4096] fp32   -> M = 8192, K = 4096
//   weight: [4096, 4096]    fp32   -> N = 4096 (row-major, K contiguous)
//   lora_A: [8, 4096]       fp32
//   lora_B: [4096, 8]       fp32
//   out:    [4, 2048, 4096] fp32
// out = x @ W^T + (16/8) * (x @ A^T) @ B^T  ==  x @ (W + 2*B@A)^T

constexpr int D_IN   = 4096;
constexpr int D_OUT  = 4096;
constexpr int RANK   = 8;
constexpr int M_ROWS = 4 * 2048;        // 8192
constexpr float LORA_SCALE = 16.0f / 8.0f;

// Scratch for the folded weight (allocation-free rule: __device__ global).
__device__ float g_weff[(size_t)D_OUT * D_IN];

// ---------------------------------------------------------------------------
// Kernel 1: W_eff = W + 2 * (B @ A).  134M FMA, trivial (<30 us).
// ---------------------------------------------------------------------------
__global__ void weff_kernel(const float* __restrict__ w,
                            const float* __restrict__ la,
                            const float* __restrict__ lb) {
    const int d = blockIdx.x * blockDim.x + threadIdx.x;   // 0..4095
    const int o = blockIdx.y;                              // 0..4095
    float acc = 0.0f;
#pragma unroll
    for (int r = 0; r < RANK; ++r)
        acc = fmaf(lb[o * RANK + r], la[r * D_IN + d], acc);
    g_weff[(size_t)o * D_IN + d] = w[(size_t)o * D_IN + d] + LORA_SCALE * acc;
}

// ---------------------------------------------------------------------------
// Packed f32x2 helpers (ptxas never auto-fuses; must come from PTX).
// ---------------------------------------------------------------------------
__device__ __forceinline__ unsigned long long pack2(float x) {
    unsigned long long r;
    asm("mov.b64 %0, {%1, %1};" : "=l"(r) : "f"(x));
    return r;
}
__device__ __forceinline__ void unpack2(unsigned long long v, float& x, float& y) {
    asm("mov.b64 {%0, %1}, %2;" : "=f"(x), "=f"(y) : "l"(v));
}
__device__ __forceinline__ unsigned long long ffma2(unsigned long long a,
                                                    unsigned long long b,
                                                    unsigned long long c) {
    unsigned long long d;
    asm("fma.rn.f32x2 %0, %1, %2, %3;" : "=l"(d) : "l"(a), "l"(b), "l"(c));
    return d;
}

// ---------------------------------------------------------------------------
// Kernel 2: C[M,N] = A[M,K] @ B[N,K]^T, fp32, 128x128x8 tiles.
// Each thread: 2x2 blocks of 4x4 outputs at rows {m0, m0+64} x cols {n0, n0+64}
// (conflict-free LDS.128 fragment layout: 16B lane stride covers all 32 banks
// per 8-lane phase; A-side is half-warp broadcast), accumulators packed f32x2
// along N. Ping-pong smem, 1 BAR/iter.
// ---------------------------------------------------------------------------
#define BM 128
#define BN 128
#define BK 8

// c[rh*4 + i][ch*2 + p] : row-half rh, row i (0..3), col-half ch, f32x2 pair p
__device__ __forceinline__ void compute_tile(const float* __restrict__ As,
                                             const float* __restrict__ Bs,
                                             unsigned long long (&c)[8][4],
                                             int m0, int n0) {
#pragma unroll
    for (int k = 0; k < BK; ++k) {
        float4 a0 = *(const float4*)(As + k * BM + m0);        // rows m0..m0+3
        float4 a1 = *(const float4*)(As + k * BM + m0 + 64);   // rows m0+64..
        ulonglong2 b0 = *(const ulonglong2*)(Bs + k * BN + n0);      // cols n0..n0+3
        ulonglong2 b1 = *(const ulonglong2*)(Bs + k * BN + n0 + 64); // cols n0+64..
        unsigned long long bb[4] = {b0.x, b0.y, b1.x, b1.y};
        float av[8] = {a0.x, a0.y, a0.z, a0.w, a1.x, a1.y, a1.z, a1.w};
#pragma unroll
        for (int i = 0; i < 8; ++i) {
            unsigned long long a2 = pack2(av[i]);
#pragma unroll
            for (int j = 0; j < 4; ++j)
                c[i][j] = ffma2(a2, bb[j], c[i][j]);
        }
    }
}

__global__ __launch_bounds__(256, 2)
void gemm_kernel(const float* __restrict__ A, float* __restrict__ C) {
    __shared__ float As[2][BK][BM];
    __shared__ float Bs[2][BK][BN];

    const int tid = threadIdx.x;
    const int bm  = blockIdx.y;
    const int bn  = blockIdx.x;

    // Global-load mapping: each thread fetches one float4 of each tile.
    const int row = tid >> 1;            // 0..127
    const int kc  = (tid & 1) * 4;       // 0 or 4

    // Compute mapping: 16x16 thread grid, 4x4 fragments at {m0,m0+64}x{n0,n0+64}.
    const int ty = tid >> 4, tx = tid & 15;
    const int m0 = ty * 4,   n0 = tx * 4;

    const float* Ag = A      + (size_t)(bm * BM + row) * D_IN + kc;
    const float* Bg = g_weff + (size_t)(bn * BN + row) * D_IN + kc;

    unsigned long long c[8][4];
#pragma unroll
    for (int i = 0; i < 8; ++i)
#pragma unroll
        for (int j = 0; j < 4; ++j) c[i][j] = 0ull;

    // Prologue: tile 0 -> smem buf 0.
    {
        float4 a4 = *(const float4*)Ag;
        float4 b4 = *(const float4*)Bg;
#pragma unroll
        for (int j = 0; j < 4; ++j) {
            As[0][kc + j][row] = ((const float*)&a4)[j];
            Bs[0][kc + j][row] = ((const float*)&b4)[j];
        }
    }
    __syncthreads();

    int buf = 0;
    const int NT = D_IN / BK;            // 512 K-tiles
    for (int t = 1; t < NT; ++t) {
        // Issue next tile's global loads early; latency hides under compute
        // (MLP=2 front-batched LDG.128, ~600cy DRAM latency vs ~2000cy compute).
        float4 na = *(const float4*)(Ag + t * BK);
        float4 nb = *(const float4*)(Bg + t * BK);

        compute_tile(&As[buf][0][0], &Bs[buf][0][0], c, m0, n0);

#pragma unroll
        for (int j = 0; j < 4; ++j) {
            As[buf ^ 1][kc + j][row] = ((const float*)&na)[j];
            Bs[buf ^ 1][kc + j][row] = ((const float*)&nb)[j];
        }
        __syncthreads();
        buf ^= 1;
    }
    compute_tile(&As[buf][0][0], &Bs[buf][0][0], c, m0, n0);

    // Epilogue: 2 row-halves x 4 rows, 2 col-halves x float4 per row.
#pragma unroll
    for (int rh = 0; rh < 2; ++rh) {
#pragma unroll
        for (int i = 0; i < 4; ++i) {
            const int r = rh * 4 + i;
            float x0, y0, x1, y1, x2, y2, x3, y3;
            unpack2(c[r][0], x0, y0);
            unpack2(c[r][1], x1, y1);
            unpack2(c[r][2], x2, y2);
            unpack2(c[r][3], x3, y3);
            float4 v0 = make_float4(x0, y0, x1, y1);   // cols n0..n0+3
            float4 v1 = make_float4(x2, y2, x3, y3);   // cols n0+64..n0+67
            float* Crow = C + (size_t)(bm * BM + m0 + rh * 64 + i) * D_OUT
                            + bn * BN + n0;
            *(float4*)(Crow)      = v0;
            *(float4*)(Crow + 64) = v1;
        }
    }
}

// ---------------------------------------------------------------------------
// Launch. Inputs in metadata order: x, weight, lora_A, lora_B.
// ---------------------------------------------------------------------------
extern "C" void kernel_launch(void* const* d_in, const int* in_sizes, int n_in,
                              void* d_out, int out_size) {
    const float* x  = (const float*)d_in[0];
    const float* w  = (const float*)d_in[1];
    const float* la = (const float*)d_in[2];
    const float* lb = (const float*)d_in[3];
    float* out = (float*)d_out;

    {
        dim3 grid(D_IN / 256, D_OUT);
        weff_kernel<<<grid, 256>>>(w, la, lb);
    }
    {
        dim3 grid(D_OUT / BN, M_ROWS / BM);   // (32, 64)
        gemm_kernel<<<grid, 256>>>(x, out);
    }
}

// round 5
// speedup vs baseline: 1.8729x; 1.8729x over previous
#include <cuda_runtime.h>
#include <cuda_bf16.h>
#include <cstdint>

// out = x @ (W + 2*B@A)^T, fp32.  M=8192, N=4096, K=4096.
// Accuracy: split x, W_eff into bf16 hi+lo; C = Xhi*Whi + Xhi*Wlo + Xlo*Whi
// as ONE GEMM over virtual K = 3*4096 (phase-indexed operand pointers).
// Tensor path: mma.sync m16n8k16 bf16 (baseline sm_80 PTX -> HMMA; tcgen05
// is rejected by this harness's sm_103 PTX target).

constexpr int D_IN   = 4096;
constexpr int D_OUT  = 4096;
constexpr int RANK   = 8;
constexpr int M_ROWS = 8192;
constexpr float LORA_SCALE = 16.0f / 8.0f;

__device__ __align__(1024) __nv_bfloat16 g_Xhi[(size_t)M_ROWS * D_IN];
__device__ __align__(1024) __nv_bfloat16 g_Xlo[(size_t)M_ROWS * D_IN];
__device__ __align__(1024) __nv_bfloat16 g_Whi[(size_t)D_OUT * D_IN];
__device__ __align__(1024) __nv_bfloat16 g_Wlo[(size_t)D_OUT * D_IN];

// ---------------------------------------------------------------------------
// Conversion kernels
// ---------------------------------------------------------------------------
__device__ __forceinline__ void split_bf16(float v, __nv_bfloat16& h, __nv_bfloat16& l) {
    h = __float2bfloat16(v);
    l = __float2bfloat16(v - __bfloat162float(h));
}

__global__ void xsplit_kernel(const float4* __restrict__ x) {
    size_t i = (size_t)blockIdx.x * blockDim.x + threadIdx.x;
    float4 v = x[i];
    __nv_bfloat16 h0, h1, h2, h3, l0, l1, l2, l3;
    split_bf16(v.x, h0, l0); split_bf16(v.y, h1, l1);
    split_bf16(v.z, h2, l2); split_bf16(v.w, h3, l3);
    __nv_bfloat162* ph = (__nv_bfloat162*)(g_Xhi + 4 * i);
    __nv_bfloat162* pl = (__nv_bfloat162*)(g_Xlo + 4 * i);
    ph[0] = __nv_bfloat162{h0, h1}; ph[1] = __nv_bfloat162{h2, h3};
    pl[0] = __nv_bfloat162{l0, l1}; pl[1] = __nv_bfloat162{l2, l3};
}

__global__ void wsplit_kernel(const float* __restrict__ w,
                              const float* __restrict__ la,
                              const float* __restrict__ lb) {
    const int d = blockIdx.x * blockDim.x + threadIdx.x;
    const int o = blockIdx.y;
    float acc = 0.0f;
#pragma unroll
    for (int r = 0; r < RANK; ++r)
        acc = fmaf(lb[o * RANK + r], la[r * D_IN + d], acc);
    float v = w[(size_t)o * D_IN + d] + LORA_SCALE * acc;
    __nv_bfloat16 h, l;
    split_bf16(v, h, l);
    g_Whi[(size_t)o * D_IN + d] = h;
    g_Wlo[(size_t)o * D_IN + d] = l;
}

// ---------------------------------------------------------------------------
// PTX primitives (all baseline sm_80 — safe at the sm_103 PTX target)
// ---------------------------------------------------------------------------
__device__ __forceinline__ uint32_t smem_u32(const void* p) {
    uint32_t a;
    asm("{ .reg .u64 t; cvta.to.shared.u64 t, %1; cvt.u32.u64 %0, t; }"
        : "=r"(a) : "l"(p));
    return a;
}
__device__ __forceinline__ void cpa16(uint32_t dst, const void* src) {
    asm volatile("cp.async.cg.shared.global [%0], [%1], 16;" :: "r"(dst), "l"(src));
}
#define CP_COMMIT() asm volatile("cp.async.commit_group;" ::: "memory")
#define CP_WAIT(n)  asm volatile("cp.async.wait_group %0;" :: "n"(n) : "memory")

__device__ __forceinline__ void ldsm_x4(uint32_t (&r)[4], uint32_t addr) {
    asm volatile("ldmatrix.sync.aligned.m8n8.x4.shared.b16 {%0,%1,%2,%3}, [%4];"
                 : "=r"(r[0]), "=r"(r[1]), "=r"(r[2]), "=r"(r[3]) : "r"(addr));
}
__device__ __forceinline__ void mma_16816(float (&d)[4], const uint32_t (&a)[4],
                                          uint32_t b0, uint32_t b1) {
    asm volatile(
        "mma.sync.aligned.m16n8k16.row.col.f32.bf16.bf16.f32 "
        "{%0,%1,%2,%3}, {%4,%5,%6,%7}, {%8,%9}, {%0,%1,%2,%3};"
        : "+f"(d[0]), "+f"(d[1]), "+f"(d[2]), "+f"(d[3])
        : "r"(a[0]), "r"(a[1]), "r"(a[2]), "r"(a[3]), "r"(b0), "r"(b1));
}

// ---------------------------------------------------------------------------
// GEMM: 128x128 CTA tile, BK=32 bf16, 8 warps (4 mwarps x 2 nwarps),
// warp tile 32x64. Smem rows 64B data + 16B pad = 80B (conflict-free LDSM).
// 4-stage cp.async ring; 384 virtual K-stages (3 phases x 128).
// ---------------------------------------------------------------------------
constexpr int BK      = 32;
constexpr int ROW_B   = 80;                 // 64B data + 16B pad
constexpr int TILE_B  = 128 * ROW_B;        // 10240
constexpr int STAGE_B = 2 * TILE_B;         // 20480 (A then B)
constexpr int NSTAGES = 4;
constexpr int SMEM_TOTAL = NSTAGES * STAGE_B;   // 81920
constexpr int KS_PER_PHASE = D_IN / BK;     // 128
constexpr int NSTG = 3 * KS_PER_PHASE;      // 384

__device__ __forceinline__ void load_stage(int s, uint32_t sb, int bm, int bn, int tid) {
    const int phase = s >> 7;               // KS_PER_PHASE = 128
    const int ks    = s & 127;
    const int slot  = s & (NSTAGES - 1);
    const __nv_bfloat16* Ap = (phase == 2) ? g_Xlo : g_Xhi;
    const __nv_bfloat16* Bp = (phase == 1) ? g_Wlo : g_Whi;
    const uint32_t stage = sb + slot * STAGE_B;
#pragma unroll
    for (int h = 0; h < 2; ++h) {           // chunks t and t+256 of each tile
        const int id  = h * 256 + tid;      // 0..511
        const int row = id >> 2, c = id & 3;
        cpa16(stage + row * ROW_B + c * 16,
              Ap + (size_t)(bm * 128 + row) * D_IN + ks * BK + c * 8);
        cpa16(stage + TILE_B + row * ROW_B + c * 16,
              Bp + (size_t)(bn * 128 + row) * D_IN + ks * BK + c * 8);
    }
    CP_COMMIT();
}

__global__ __launch_bounds__(256, 2)
void gemm_tc(float* __restrict__ C) {
    extern __shared__ __align__(128) char smem[];
    const uint32_t sb = smem_u32(smem);
    const int tid = threadIdx.x, wid = tid >> 5, lid = tid & 31;
    const int bn = blockIdx.x, bm = blockIdx.y;
    const int mw = wid & 3, nw = wid >> 2;  // 4 mwarps x 2 nwarps

    // Per-lane ldmatrix base addresses (within a stage, k16-step 0).
    // A (x4, 16x16): lanes 0-15 rows +0..15 khalf 0; lanes 16-31 same rows khalf 1.
    const uint32_t aBase = (mw * 32 + (lid & 15)) * ROW_B + (lid >> 4) * 16;
    // B (x4, 2 nfrags): l0-7 n+0..7 k0; l8-15 n+0..7 k8; l16-23 n+8..15 k0; l24-31 k8.
    const uint32_t bBase = TILE_B + (nw * 64 + (lid >> 4) * 8 + (lid & 7)) * ROW_B
                         + ((lid >> 3) & 1) * 16;

    float acc[2][8][4];
#pragma unroll
    for (int f = 0; f < 2; ++f)
#pragma unroll
        for (int n = 0; n < 8; ++n)
#pragma unroll
            for (int j = 0; j < 4; ++j) acc[f][n][j] = 0.0f;

    load_stage(0, sb, bm, bn, tid);
    load_stage(1, sb, bm, bn, tid);
    load_stage(2, sb, bm, bn, tid);

    for (int s = 0; s < NSTG; ++s) {
        if (s + 3 < NSTG) { load_stage(s + 3, sb, bm, bn, tid); CP_WAIT(3); }
        else if (s == NSTG - 3) { CP_WAIT(2); }
        else if (s == NSTG - 2) { CP_WAIT(1); }
        else                    { CP_WAIT(0); }
        __syncthreads();

        const uint32_t st = sb + (s & (NSTAGES - 1)) * STAGE_B;
#pragma unroll
        for (int kk = 0; kk < 2; ++kk) {    // two k16 steps per BK=32 stage
            uint32_t a[2][4], br[4][4];
#pragma unroll
            for (int f = 0; f < 2; ++f)
                ldsm_x4(a[f], st + aBase + f * 16 * ROW_B + kk * 32);
#pragma unroll
            for (int pr = 0; pr < 4; ++pr)
                ldsm_x4(br[pr], st + bBase + pr * 16 * ROW_B + kk * 32);
#pragma unroll
            for (int f = 0; f < 2; ++f)
#pragma unroll
                for (int n = 0; n < 8; ++n)
                    mma_16816(acc[f][n], a[f], br[n >> 1][(n & 1) * 2],
                                               br[n >> 1][(n & 1) * 2 + 1]);
        }
        __syncthreads();
    }

    // Epilogue: lane l owns rows base_r, base_r+8; cols nf*8 + 2*(l&3).
    const int r0 = bm * 128 + mw * 32 + (lid >> 2);
    const int c0 = bn * 128 + nw * 64 + (lid & 3) * 2;
#pragma unroll
    for (int f = 0; f < 2; ++f)
#pragma unroll
        for (int n = 0; n < 8; ++n) {
            float* p = C + (size_t)(r0 + f * 16) * D_OUT + c0 + n * 8;
            *(float2*)p                    = make_float2(acc[f][n][0], acc[f][n][1]);
            *(float2*)(p + 8 * (size_t)D_OUT) = make_float2(acc[f][n][2], acc[f][n][3]);
        }
}

// ---------------------------------------------------------------------------
// Launch. Inputs in metadata order: x, weight, lora_A, lora_B.
// ---------------------------------------------------------------------------
extern "C" void kernel_launch(void* const* d_in, const int* in_sizes, int n_in,
                              void* d_out, int out_size) {
    const float* x  = (const float*)d_in[0];
    const float* w  = (const float*)d_in[1];
    const float* la = (const float*)d_in[2];
    const float* lb = (const float*)d_in[3];
    float* out = (float*)d_out;

    cudaFuncSetAttribute(gemm_tc, cudaFuncAttributeMaxDynamicSharedMemorySize, SMEM_TOTAL);

    {
        const size_t n4 = (size_t)M_ROWS * D_IN / 4;
        xsplit_kernel<<<(unsigned)(n4 / 256), 256>>>((const float4*)x);
    }
    {
        dim3 grid(D_IN / 256, D_OUT);
        wsplit_kernel<<<grid, 256>>>(w, la, lb);
    }
    {
        dim3 grid(D_OUT / 128, M_ROWS / 128);   // (32, 64)
        gemm_tc<<<grid, 256, SMEM_TOTAL>>>(out);
    }
}

// round 7
// speedup vs baseline: 3.2733x; 1.7477x over previous
#include <cuda_runtime.h>
#include <cuda_fp16.h>
#include <cstdint>

// out = x @ (W + 2*B@A)^T, fp32.  M=8192, N=4096, K=4096.
// Accuracy scheme (validated error calculus from R5):
//   X = Xhi + Xlo (both fp16; fp16 products are EXACT in fp32 accum),
//   W -> single fp16.  C = Xhi*W^T + Xlo*W^T.  Residual error = W rounding
//   only ~ 0.58*2^-11 ~ 2.8e-4 (L2) < 1e-3 tolerance.
// Tensor path: mma.sync m16n8k16 f16 (baseline PTX; tcgen05 rejected at the
// harness's sm_103 PTX target).
// Structure: ks-major groups {Ahi, Alo, B}: B tile loaded once, used by both
// A passes (B LDSM fragments reused in registers across the two MMA sets).

constexpr int D_IN   = 4096;
constexpr int D_OUT  = 4096;
constexpr int RANK   = 8;
constexpr int M_ROWS = 8192;
constexpr float LORA_SCALE = 16.0f / 8.0f;

__device__ __align__(1024) __half g_Xhi[(size_t)M_ROWS * D_IN];
__device__ __align__(1024) __half g_Xlo[(size_t)M_ROWS * D_IN];
__device__ __align__(1024) __half g_Wh [(size_t)D_OUT * D_IN];

// ---------------------------------------------------------------------------
// Conversion kernels
// ---------------------------------------------------------------------------
__global__ void xsplit_kernel(const float4* __restrict__ x) {
    size_t i = (size_t)blockIdx.x * blockDim.x + threadIdx.x;
    float4 v = x[i];
    __half h0 = __float2half(v.x), h1 = __float2half(v.y),
           h2 = __float2half(v.z), h3 = __float2half(v.w);
    __half l0 = __float2half(v.x - __half2float(h0));
    __half l1 = __float2half(v.y - __half2float(h1));
    __half l2 = __float2half(v.z - __half2float(h2));
    __half l3 = __float2half(v.w - __half2float(h3));
    __half2* ph = (__half2*)(g_Xhi + 4 * i);
    __half2* pl = (__half2*)(g_Xlo + 4 * i);
    ph[0] = __half2{h0, h1}; ph[1] = __half2{h2, h3};
    pl[0] = __half2{l0, l1}; pl[1] = __half2{l2, l3};
}

__global__ void wfold_kernel(const float* __restrict__ w,
                             const float* __restrict__ la,
                             const float* __restrict__ lb) {
    const int d = blockIdx.x * blockDim.x + threadIdx.x;
    const int o = blockIdx.y;
    float acc = 0.0f;
#pragma unroll
    for (int r = 0; r < RANK; ++r)
        acc = fmaf(lb[o * RANK + r], la[r * D_IN + d], acc);
    g_Wh[(size_t)o * D_IN + d] =
        __float2half(w[(size_t)o * D_IN + d] + LORA_SCALE * acc);
}

// ---------------------------------------------------------------------------
// PTX primitives (baseline sm_80 — safe at the sm_103 PTX target)
// ---------------------------------------------------------------------------
__device__ __forceinline__ uint32_t smem_u32(const void* p) {
    uint32_t a;
    asm("{ .reg .u64 t; cvta.to.shared.u64 t, %1; cvt.u32.u64 %0, t; }"
        : "=r"(a) : "l"(p));
    return a;
}
__device__ __forceinline__ void cpa16(uint32_t dst, const void* src) {
    asm volatile("cp.async.cg.shared.global [%0], [%1], 16;" :: "r"(dst), "l"(src));
}
#define CP_COMMIT() asm volatile("cp.async.commit_group;" ::: "memory")
#define CP_WAIT(n)  asm volatile("cp.async.wait_group %0;" :: "n"(n) : "memory")

__device__ __forceinline__ void ldsm_x4(uint32_t (&r)[4], uint32_t addr) {
    asm volatile("ldmatrix.sync.aligned.m8n8.x4.shared.b16 {%0,%1,%2,%3}, [%4];"
                 : "=r"(r[0]), "=r"(r[1]), "=r"(r[2]), "=r"(r[3]) : "r"(addr));
}
__device__ __forceinline__ void mma_16816(float (&d)[4], const uint32_t (&a)[4],
                                          uint32_t b0, uint32_t b1) {
    asm volatile(
        "mma.sync.aligned.m16n8k16.row.col.f32.f16.f16.f32 "
        "{%0,%1,%2,%3}, {%4,%5,%6,%7}, {%8,%9}, {%0,%1,%2,%3};"
        : "+f"(d[0]), "+f"(d[1]), "+f"(d[2]), "+f"(d[3])
        : "r"(a[0]), "r"(a[1]), "r"(a[2]), "r"(a[3]), "r"(b0), "r"(b1));
}

// ---------------------------------------------------------------------------
// GEMM: 128x128 CTA tile, BK=32 halves, 8 warps (4 mwarps x 2 nwarps),
// warp tile 32x64. Smem rows 64B data + 16B pad (conflict-free LDSM/cp.async).
// Group = {Ahi, Alo, B} tiles; 3-slot ring; 128 ks-groups; B frags reused.
// ---------------------------------------------------------------------------
constexpr int BK      = 32;
constexpr int ROW_B   = 80;                  // 64B data + 16B pad
constexpr int TILE_B  = 128 * ROW_B;         // 10240
constexpr int GROUP_B = 3 * TILE_B;          // 30720 (Ahi, Alo, B)
constexpr int NSLOTS  = 3;
constexpr int SMEM_TOTAL = NSLOTS * GROUP_B; // 92160
constexpr int NG      = D_IN / BK;           // 128 groups

__device__ __forceinline__ void load_group(int g, uint32_t sb, int bm, int bn, int tid) {
    const int slot = g % NSLOTS;
    const uint32_t base = sb + slot * GROUP_B;
    const __half* mats[3] = {g_Xhi, g_Xlo, g_Wh};
    const int     rows[3] = {bm * 128, bm * 128, bn * 128};
#pragma unroll
    for (int t = 0; t < 3; ++t) {
        const __half* mat = mats[t] + (size_t)rows[t] * D_IN + g * BK;
        const uint32_t db = base + t * TILE_B;
        // 512 16B-chunks per tile (128 rows x 4), 256 threads -> 2 each.
#pragma unroll
        for (int h = 0; h < 2; ++h) {
            const int id  = h * 256 + tid;
            const int row = id >> 2, c = id & 3;
            cpa16(db + row * ROW_B + c * 16,
                  mat + (size_t)row * D_IN + c * 8);
        }
    }
    CP_COMMIT();
}

__global__ __launch_bounds__(256, 2)
void gemm_tc(float* __restrict__ C) {
    extern __shared__ __align__(128) char smem[];
    const uint32_t sb = smem_u32(smem);
    const int tid = threadIdx.x, wid = tid >> 5, lid = tid & 31;
    const int bn = blockIdx.x, bm = blockIdx.y;
    const int mw = wid & 3, nw = wid >> 2;   // 4 mwarps x 2 nwarps

    // ldmatrix lane bases (within a tile, k16-step 0).
    const uint32_t aBase = (mw * 32 + (lid & 15)) * ROW_B + (lid >> 4) * 16;
    const uint32_t bBase = 2 * TILE_B
                         + (nw * 64 + (lid >> 4) * 8 + (lid & 7)) * ROW_B
                         + ((lid >> 3) & 1) * 16;

    float acc[2][8][4];
#pragma unroll
    for (int f = 0; f < 2; ++f)
#pragma unroll
        for (int n = 0; n < 8; ++n)
#pragma unroll
            for (int j = 0; j < 4; ++j) acc[f][n][j] = 0.0f;

    load_group(0, sb, bm, bn, tid);
    load_group(1, sb, bm, bn, tid);
    load_group(2, sb, bm, bn, tid);

    for (int s = 0; s < NG; ++s) {
        if (s < NG - 2)      CP_WAIT(2);
        else if (s == NG - 2) CP_WAIT(1);
        else                  CP_WAIT(0);
        __syncthreads();

        const uint32_t st = sb + (s % NSLOTS) * GROUP_B;
#pragma unroll
        for (int kk = 0; kk < 2; ++kk) {     // two k16 steps per BK=32 group
            uint32_t ah[2][4], al[2][4], br[4][4];
#pragma unroll
            for (int f = 0; f < 2; ++f) {
                ldsm_x4(ah[f], st + aBase + f * 16 * ROW_B + kk * 32);
                ldsm_x4(al[f], st + TILE_B + aBase + f * 16 * ROW_B + kk * 32);
            }
#pragma unroll
            for (int pr = 0; pr < 4; ++pr)
                ldsm_x4(br[pr], st + bBase + pr * 16 * ROW_B + kk * 32);
            // Both A passes accumulate into the same C (C = (Xhi+Xlo) * W^T).
#pragma unroll
            for (int f = 0; f < 2; ++f)
#pragma unroll
                for (int n = 0; n < 8; ++n) {
                    const uint32_t b0 = br[n >> 1][(n & 1) * 2];
                    const uint32_t b1 = br[n >> 1][(n & 1) * 2 + 1];
                    mma_16816(acc[f][n], ah[f], b0, b1);
                    mma_16816(acc[f][n], al[f], b0, b1);
                }
        }
        __syncthreads();
        if (s + NSLOTS < NG) load_group(s + NSLOTS, sb, bm, bn, tid);
    }

    // Epilogue: lane l owns rows r0, r0+8 per frag; cols c0 + n*8.
    const int r0 = bm * 128 + mw * 32 + (lid >> 2);
    const int c0 = bn * 128 + nw * 64 + (lid & 3) * 2;
#pragma unroll
    for (int f = 0; f < 2; ++f)
#pragma unroll
        for (int n = 0; n < 8; ++n) {
            float* p = C + (size_t)(r0 + f * 16) * D_OUT + c0 + n * 8;
            *(float2*)p                       = make_float2(acc[f][n][0], acc[f][n][1]);
            *(float2*)(p + 8 * (size_t)D_OUT) = make_float2(acc[f][n][2], acc[f][n][3]);
        }
}

// ---------------------------------------------------------------------------
// Launch. Inputs in metadata order: x, weight, lora_A, lora_B.
// ---------------------------------------------------------------------------
extern "C" void kernel_launch(void* const* d_in, const int* in_sizes, int n_in,
                              void* d_out, int out_size) {
    const float* x  = (const float*)d_in[0];
    const float* w  = (const float*)d_in[1];
    const float* la = (const float*)d_in[2];
    const float* lb = (const float*)d_in[3];
    float* out = (float*)d_out;

    cudaFuncSetAttribute(gemm_tc, cudaFuncAttributeMaxDynamicSharedMemorySize, SMEM_TOTAL);

    {
        const size_t n4 = (size_t)M_ROWS * D_IN / 4;
        xsplit_kernel<<<(unsigned)(n4 / 256), 256>>>((const float4*)x);
    }
    {
        dim3 grid(D_IN / 256, D_OUT);
        wfold_kernel<<<grid, 256>>>(w, la, lb);
    }
    {
        dim3 grid(D_OUT / 128, M_ROWS / 128);   // (32, 64)
        gemm_tc<<<grid, 256, SMEM_TOTAL>>>(out);
    }
}

// round 13
// speedup vs baseline: 5.6269x; 1.7190x over previous
#include <cuda_runtime.h>
#include <cuda_fp16.h>
#include <cstdint>

// out = x @ (W + 2*B@A)^T, fp32.  M=8192, N=4096, K=4096.
// Accuracy (calibrated in R5/R7): single-pass fp16. Measured W-only rounding
// error = 2.08e-4; adding independent X-rounding term of equal size gives
// ~sqrt(2)*2.08e-4 ~ 2.9e-4 < 1e-3 tolerance (3.4x margin).
// Tensor path: mma.sync m16n8k16 f16 (baseline PTX; tcgen05 rejected at the
// harness's sm_103 PTX target).
// Pipeline: group {A, B} (2 tiles, 20.5KB), 4-slot cp.async ring, ONE
// __syncthreads per group (slot of s+3 == slot of s-1, whose readers all
// passed the current barrier).

constexpr int D_IN   = 4096;
constexpr int D_OUT  = 4096;
constexpr int RANK   = 8;
constexpr int M_ROWS = 8192;
constexpr float LORA_SCALE = 16.0f / 8.0f;

__device__ __align__(1024) __half g_Xh[(size_t)M_ROWS * D_IN];
__device__ __align__(1024) __half g_Wh[(size_t)D_OUT * D_IN];

// ---------------------------------------------------------------------------
// Conversion kernels
// ---------------------------------------------------------------------------
__global__ void xconv_kernel(const float4* __restrict__ x) {
    size_t i = (size_t)blockIdx.x * blockDim.x + threadIdx.x;
    float4 v = x[i];
    __half2* p = (__half2*)(g_Xh + 4 * i);
    p[0] = __half2{__float2half(v.x), __float2half(v.y)};
    p[1] = __half2{__float2half(v.z), __float2half(v.w)};
}

__global__ void wfold_kernel(const float* __restrict__ w,
                             const float* __restrict__ la,
                             const float* __restrict__ lb) {
    const int d = blockIdx.x * blockDim.x + threadIdx.x;
    const int o = blockIdx.y;
    float acc = 0.0f;
#pragma unroll
    for (int r = 0; r < RANK; ++r)
        acc = fmaf(lb[o * RANK + r], la[r * D_IN + d], acc);
    g_Wh[(size_t)o * D_IN + d] =
        __float2half(w[(size_t)o * D_IN + d] + LORA_SCALE * acc);
}

// ---------------------------------------------------------------------------
// PTX primitives (baseline sm_80 — safe at the sm_103 PTX target)
// ---------------------------------------------------------------------------
__device__ __forceinline__ uint32_t smem_u32(const void* p) {
    uint32_t a;
    asm("{ .reg .u64 t; cvta.to.shared.u64 t, %1; cvt.u32.u64 %0, t; }"
        : "=r"(a) : "l"(p));
    return a;
}
__device__ __forceinline__ void cpa16(uint32_t dst, const void* src) {
    asm volatile("cp.async.cg.shared.global [%0], [%1], 16;" :: "r"(dst), "l"(src));
}
#define CP_COMMIT() asm volatile("cp.async.commit_group;" ::: "memory")
#define CP_WAIT(n)  asm volatile("cp.async.wait_group %0;" :: "n"(n) : "memory")

__device__ __forceinline__ void ldsm_x4(uint32_t (&r)[4], uint32_t addr) {
    asm volatile("ldmatrix.sync.aligned.m8n8.x4.shared.b16 {%0,%1,%2,%3}, [%4];"
                 : "=r"(r[0]), "=r"(r[1]), "=r"(r[2]), "=r"(r[3]) : "r"(addr));
}
__device__ __forceinline__ void mma_16816(float (&d)[4], const uint32_t (&a)[4],
                                          uint32_t b0, uint32_t b1) {
    asm volatile(
        "mma.sync.aligned.m16n8k16.row.col.f32.f16.f16.f32 "
        "{%0,%1,%2,%3}, {%4,%5,%6,%7}, {%8,%9}, {%0,%1,%2,%3};"
        : "+f"(d[0]), "+f"(d[1]), "+f"(d[2]), "+f"(d[3])
        : "r"(a[0]), "r"(a[1]), "r"(a[2]), "r"(a[3]), "r"(b0), "r"(b1));
}

// ---------------------------------------------------------------------------
// GEMM: 128x128 CTA tile, BK=32 halves, 8 warps (4 mwarps x 2 nwarps),
// warp tile 32x64. Smem rows 64B data + 16B pad (conflict-free LDSM/cp.async).
// Group = {A, B}; 4-slot ring; 128 groups; 1 sync/group.
// ---------------------------------------------------------------------------
constexpr int BK      = 32;
constexpr int ROW_B   = 80;                  // 64B data + 16B pad
constexpr int TILE_B  = 128 * ROW_B;         // 10240
constexpr int GROUP_B = 2 * TILE_B;          // 20480 (A, B)
constexpr int NSLOTS  = 4;
constexpr int SMEM_TOTAL = NSLOTS * GROUP_B; // 81920
constexpr int NG      = D_IN / BK;           // 128 groups

__device__ __forceinline__ void load_group(int g, uint32_t sb, int bm, int bn, int tid) {
    const int slot = g & (NSLOTS - 1);
    const uint32_t base = sb + slot * GROUP_B;
    const __half* mats[2] = {g_Xh, g_Wh};
    const int     rows[2] = {bm * 128, bn * 128};
#pragma unroll
    for (int t = 0; t < 2; ++t) {
        const __half* mat = mats[t] + (size_t)rows[t] * D_IN + g * BK;
        const uint32_t db = base + t * TILE_B;
        // 512 16B-chunks per tile (128 rows x 4), 256 threads -> 2 each.
#pragma unroll
        for (int h = 0; h < 2; ++h) {
            const int id  = h * 256 + tid;
            const int row = id >> 2, c = id & 3;
            cpa16(db + row * ROW_B + c * 16,
                  mat + (size_t)row * D_IN + c * 8);
        }
    }
    CP_COMMIT();
}

__global__ __launch_bounds__(256, 2)
void gemm_tc(float* __restrict__ C) {
    extern __shared__ __align__(128) char smem[];
    const uint32_t sb = smem_u32(smem);
    const int tid = threadIdx.x, wid = tid >> 5, lid = tid & 31;
    const int bn = blockIdx.x, bm = blockIdx.y;
    const int mw = wid & 3, nw = wid >> 2;   // 4 mwarps x 2 nwarps

    // ldmatrix lane bases (within a tile, k16-step 0).
    const uint32_t aBase = (mw * 32 + (lid & 15)) * ROW_B + (lid >> 4) * 16;
    const uint32_t bBase = TILE_B
                         + (nw * 64 + (lid >> 4) * 8 + (lid & 7)) * ROW_B
                         + ((lid >> 3) & 1) * 16;

    float acc[2][8][4];
#pragma unroll
    for (int f = 0; f < 2; ++f)
#pragma unroll
        for (int n = 0; n < 8; ++n)
#pragma unroll
            for (int j = 0; j < 4; ++j) acc[f][n][j] = 0.0f;

    load_group(0, sb, bm, bn, tid);
    load_group(1, sb, bm, bn, tid);
    load_group(2, sb, bm, bn, tid);

    for (int s = 0; s < NG; ++s) {
        if (s < NG - 2)       CP_WAIT(2);
        else if (s == NG - 2) CP_WAIT(1);
        else                  CP_WAIT(0);
        __syncthreads();
        // Slot of s+3 == slot of s-1; all warps finished reading s-1 before
        // this barrier, so its slot is safe to refill now (single sync/group).
        if (s + 3 < NG) load_group(s + 3, sb, bm, bn, tid);

        const uint32_t st = sb + (s & (NSLOTS - 1)) * GROUP_B;
#pragma unroll
        for (int kk = 0; kk < 2; ++kk) {     // two k16 steps per BK=32 group
            uint32_t a[2][4], br[4][4];
#pragma unroll
            for (int f = 0; f < 2; ++f)
                ldsm_x4(a[f], st + aBase + f * 16 * ROW_B + kk * 32);
#pragma unroll
            for (int pr = 0; pr < 4; ++pr)
                ldsm_x4(br[pr], st + bBase + pr * 16 * ROW_B + kk * 32);
#pragma unroll
            for (int f = 0; f < 2; ++f)
#pragma unroll
                for (int n = 0; n < 8; ++n)
                    mma_16816(acc[f][n], a[f], br[n >> 1][(n & 1) * 2],
                                                br[n >> 1][(n & 1) * 2 + 1]);
        }
    }

    // Epilogue: lane l owns rows r0, r0+8 per frag; cols c0 + n*8.
    const int r0 = bm * 128 + mw * 32 + (lid >> 2);
    const int c0 = bn * 128 + nw * 64 + (lid & 3) * 2;
#pragma unroll
    for (int f = 0; f < 2; ++f)
#pragma unroll
        for (int n = 0; n < 8; ++n) {
            float* p = C + (size_t)(r0 + f * 16) * D_OUT + c0 + n * 8;
            *(float2*)p                       = make_float2(acc[f][n][0], acc[f][n][1]);
            *(float2*)(p + 8 * (size_t)D_OUT) = make_float2(acc[f][n][2], acc[f][n][3]);
        }
}

// ---------------------------------------------------------------------------
// Launch. Inputs in metadata order: x, weight, lora_A, lora_B.
// ---------------------------------------------------------------------------
extern "C" void kernel_launch(void* const* d_in, const int* in_sizes, int n_in,
                              void* d_out, int out_size) {
    const float* x  = (const float*)d_in[0];
    const float* w  = (const float*)d_in[1];
    const float* la = (const float*)d_in[2];
    const float* lb = (const float*)d_in[3];
    float* out = (float*)d_out;

    cudaFuncSetAttribute(gemm_tc, cudaFuncAttributeMaxDynamicSharedMemorySize, SMEM_TOTAL);

    {
        const size_t n4 = (size_t)M_ROWS * D_IN / 4;
        xconv_kernel<<<(unsigned)(n4 / 256), 256>>>((const float4*)x);
    }
    {
        dim3 grid(D_IN / 256, D_OUT);
        wfold_kernel<<<grid, 256>>>(w, la, lb);
    }
    {
        dim3 grid(D_OUT / 128, M_ROWS / 128);   // (32, 64)
        gemm_tc<<<grid, 256, SMEM_TOTAL>>>(out);
    }
}

// round 16
// speedup vs baseline: 6.5659x; 1.1669x over previous
#include <cuda_runtime.h>
#include <cuda_fp16.h>
#include <cstdint>

// out = x @ (W + 2*B@A)^T, fp32.  M=8192, N=4096, K=4096.
// Accuracy (calibrated exactly: R13 measured 2.9367e-4 vs predicted 2.94e-4):
// single-pass fp16, W+X rounding only.
// Tensor path: mma.sync m16n8k16 f16 (baseline PTX; tcgen05 rejected at the
// harness's sm_103 PTX target). Measured fallback HMMA rate ~3.2-3.9
// cyc/HMMA/SM across R5/R7/R13 -> issue-bound; this round raises the
// MMA/LDSM ratio (warp tile 32x64 -> 64x64: 16 MMA/6 ldsm -> 32 MMA/8 ldsm).
// 128x128 CTA tile, 4 warps (2x2), 4-slot cp.async ring, 1 sync/group.

constexpr int D_IN   = 4096;
constexpr int D_OUT  = 4096;
constexpr int RANK   = 8;
constexpr int M_ROWS = 8192;
constexpr float LORA_SCALE = 16.0f / 8.0f;

__device__ __align__(1024) __half g_Xh[(size_t)M_ROWS * D_IN];
__device__ __align__(1024) __half g_Wh[(size_t)D_OUT * D_IN];

// ---------------------------------------------------------------------------
// Conversion kernels
// ---------------------------------------------------------------------------
__global__ void xconv_kernel(const float4* __restrict__ x) {
    size_t i = (size_t)blockIdx.x * blockDim.x + threadIdx.x;
    float4 v = x[i];
    __half2* p = (__half2*)(g_Xh + 4 * i);
    p[0] = __half2{__float2half(v.x), __float2half(v.y)};
    p[1] = __half2{__float2half(v.z), __float2half(v.w)};
}

__global__ void wfold_kernel(const float* __restrict__ w,
                             const float* __restrict__ la,
                             const float* __restrict__ lb) {
    const int d = blockIdx.x * blockDim.x + threadIdx.x;
    const int o = blockIdx.y;
    float acc = 0.0f;
#pragma unroll
    for (int r = 0; r < RANK; ++r)
        acc = fmaf(lb[o * RANK + r], la[r * D_IN + d], acc);
    g_Wh[(size_t)o * D_IN + d] =
        __float2half(w[(size_t)o * D_IN + d] + LORA_SCALE * acc);
}

// ---------------------------------------------------------------------------
// PTX primitives (baseline sm_80 — safe at the sm_103 PTX target)
// ---------------------------------------------------------------------------
__device__ __forceinline__ uint32_t smem_u32(const void* p) {
    uint32_t a;
    asm("{ .reg .u64 t; cvta.to.shared.u64 t, %1; cvt.u32.u64 %0, t; }"
        : "=r"(a) : "l"(p));
    return a;
}
__device__ __forceinline__ void cpa16(uint32_t dst, const void* src) {
    asm volatile("cp.async.cg.shared.global [%0], [%1], 16;" :: "r"(dst), "l"(src));
}
#define CP_COMMIT() asm volatile("cp.async.commit_group;" ::: "memory")
#define CP_WAIT(n)  asm volatile("cp.async.wait_group %0;" :: "n"(n) : "memory")

__device__ __forceinline__ void ldsm_x4(uint32_t (&r)[4], uint32_t addr) {
    asm volatile("ldmatrix.sync.aligned.m8n8.x4.shared.b16 {%0,%1,%2,%3}, [%4];"
                 : "=r"(r[0]), "=r"(r[1]), "=r"(r[2]), "=r"(r[3]) : "r"(addr));
}
__device__ __forceinline__ void mma_16816(float (&d)[4], const uint32_t (&a)[4],
                                          uint32_t b0, uint32_t b1) {
    asm volatile(
        "mma.sync.aligned.m16n8k16.row.col.f32.f16.f16.f32 "
        "{%0,%1,%2,%3}, {%4,%5,%6,%7}, {%8,%9}, {%0,%1,%2,%3};"
        : "+f"(d[0]), "+f"(d[1]), "+f"(d[2]), "+f"(d[3])
        : "r"(a[0]), "r"(a[1]), "r"(a[2]), "r"(a[3]), "r"(b0), "r"(b1));
}

// ---------------------------------------------------------------------------
// GEMM: 128x128 CTA tile, BK=32 halves, 4 warps (2 mwarps x 2 nwarps),
// warp tile 64x64. Smem rows 64B data + 16B pad (conflict-free LDSM/cp.async).
// Group = {A, B}; 4-slot ring; 128 groups; 1 sync/group.
// ---------------------------------------------------------------------------
constexpr int BK      = 32;
constexpr int ROW_B   = 80;                  // 64B data + 16B pad
constexpr int TILE_B  = 128 * ROW_B;         // 10240
constexpr int GROUP_B = 2 * TILE_B;          // 20480 (A, B)
constexpr int NSLOTS  = 4;
constexpr int SMEM_TOTAL = NSLOTS * GROUP_B; // 81920
constexpr int NG      = D_IN / BK;           // 128 groups
constexpr int NTHREADS = 128;                // 4 warps

__device__ __forceinline__ void load_group(int g, uint32_t sb, int bm, int bn, int tid) {
    const int slot = g & (NSLOTS - 1);
    const uint32_t base = sb + slot * GROUP_B;
    const __half* mats[2] = {g_Xh, g_Wh};
    const int     rows[2] = {bm * 128, bn * 128};
#pragma unroll
    for (int t = 0; t < 2; ++t) {
        const __half* mat = mats[t] + (size_t)rows[t] * D_IN + g * BK;
        const uint32_t db = base + t * TILE_B;
        // 512 16B-chunks per tile (128 rows x 4), 128 threads -> 4 each.
#pragma unroll
        for (int h = 0; h < 4; ++h) {
            const int id  = h * NTHREADS + tid;   // 0..511
            const int row = id >> 2, c = id & 3;
            cpa16(db + row * ROW_B + c * 16,
                  mat + (size_t)row * D_IN + c * 8);
        }
    }
    CP_COMMIT();
}

__global__ __launch_bounds__(NTHREADS, 2)
void gemm_tc(float* __restrict__ C) {
    extern __shared__ __align__(128) char smem[];
    const uint32_t sb = smem_u32(smem);
    const int tid = threadIdx.x, wid = tid >> 5, lid = tid & 31;
    const int bn = blockIdx.x, bm = blockIdx.y;
    const int mw = wid & 1, nw = wid >> 1;   // 2 mwarps x 2 nwarps

    // ldmatrix lane bases (within a tile, k16-step 0).
    const uint32_t aBase = (mw * 64 + (lid & 15)) * ROW_B + (lid >> 4) * 16;
    const uint32_t bBase = TILE_B
                         + (nw * 64 + (lid >> 4) * 8 + (lid & 7)) * ROW_B
                         + ((lid >> 3) & 1) * 16;

    // acc[f][n]: A row-frag f (16 rows each, 4 frags = 64 rows),
    //            B col n (8 cols each, 8 = 64 cols).
    float acc[4][8][4];
#pragma unroll
    for (int f = 0; f < 4; ++f)
#pragma unroll
        for (int n = 0; n < 8; ++n)
#pragma unroll
            for (int j = 0; j < 4; ++j) acc[f][n][j] = 0.0f;

    load_group(0, sb, bm, bn, tid);
    load_group(1, sb, bm, bn, tid);
    load_group(2, sb, bm, bn, tid);

    for (int s = 0; s < NG; ++s) {
        if (s < NG - 2)       CP_WAIT(2);
        else if (s == NG - 2) CP_WAIT(1);
        else                  CP_WAIT(0);
        __syncthreads();
        // Slot of s+3 == slot of s-1; all warps finished reading s-1 before
        // this barrier, so its slot is safe to refill now (single sync/group).
        if (s + 3 < NG) load_group(s + 3, sb, bm, bn, tid);

        const uint32_t st = sb + (s & (NSLOTS - 1)) * GROUP_B;
#pragma unroll
        for (int kk = 0; kk < 2; ++kk) {     // two k16 steps per BK=32 group
            uint32_t a[4][4], br[4][4];
#pragma unroll
            for (int f = 0; f < 4; ++f)
                ldsm_x4(a[f], st + aBase + f * 16 * ROW_B + kk * 32);
#pragma unroll
            for (int pr = 0; pr < 4; ++pr)
                ldsm_x4(br[pr], st + bBase + pr * 16 * ROW_B + kk * 32);
#pragma unroll
            for (int f = 0; f < 4; ++f)
#pragma unroll
                for (int n = 0; n < 8; ++n)
                    mma_16816(acc[f][n], a[f], br[n >> 1][(n & 1) * 2],
                                                br[n >> 1][(n & 1) * 2 + 1]);
        }
    }

    // Epilogue: lane l owns rows r0 + f*16 (+0, +8); cols c0 + n*8.
    const int r0 = bm * 128 + mw * 64 + (lid >> 2);
    const int c0 = bn * 128 + nw * 64 + (lid & 3) * 2;
#pragma unroll
    for (int f = 0; f < 4; ++f)
#pragma unroll
        for (int n = 0; n < 8; ++n) {
            float* p = C + (size_t)(r0 + f * 16) * D_OUT + c0 + n * 8;
            *(float2*)p                       = make_float2(acc[f][n][0], acc[f][n][1]);
            *(float2*)(p + 8 * (size_t)D_OUT) = make_float2(acc[f][n][2], acc[f][n][3]);
        }
}

// ---------------------------------------------------------------------------
// Launch. Inputs in metadata order: x, weight, lora_A, lora_B.
// ---------------------------------------------------------------------------
extern "C" void kernel_launch(void* const* d_in, const int* in_sizes, int n_in,
                              void* d_out, int out_size) {
    const float* x  = (const float*)d_in[0];
    const float* w  = (const float*)d_in[1];
    const float* la = (const float*)d_in[2];
    const float* lb = (const float*)d_in[3];
    float* out = (float*)d_out;

    cudaFuncSetAttribute(gemm_tc, cudaFuncAttributeMaxDynamicSharedMemorySize, SMEM_TOTAL);

    {
        const size_t n4 = (size_t)M_ROWS * D_IN / 4;
        xconv_kernel<<<(unsigned)(n4 / 256), 256>>>((const float4*)x);
    }
    {
        dim3 grid(D_IN / 256, D_OUT);
        wfold_kernel<<<grid, 256>>>(w, la, lb);
    }
    {
        dim3 grid(D_OUT / 128, M_ROWS / 128);   // (32, 64)
        gemm_tc<<<grid, NTHREADS, SMEM_TOTAL>>>(out);
    }
}